// round 2
// baseline (speedup 1.0000x reference)
#include <cuda_runtime.h>

#define IS      256
#define TILE    16
#define NTILEX  (IS / TILE)          // 16
#define NSLICE  8
#define CHUNK   256
#define RTHREADS 64
#define NF_MAX  24000
#define FARV    100.0f
#define NEARV   0.1f

// Per-face preprocessed data (sign-premultiplied edge equations + depth plane + bbox).
__device__ float4 g_e0[NF_MAX];
__device__ float4 g_e1[NF_MAX];
__device__ float4 g_e2[NF_MAX];
__device__ float4 g_bb[NF_MAX];
__device__ int    g_is64;

__global__ void init_kernel(int* __restrict__ outi, int n)
{
    int i = blockIdx.x * blockDim.x + threadIdx.x;
    if (i < n) outi[i] = __float_as_int(FARV);
}

// Detect whether the face-index buffer is int64 (odd int32 words all zero)
// or int32. Random indices in [0,10000) make this heuristic reliable.
__global__ void detect_kernel(const int* __restrict__ faces32, int nwords)
{
    int nz = 0;
    int lim = nwords < 2048 ? nwords : 2048;
    for (int i = 1; i < lim; i += 2) nz += (faces32[i] != 0);
    g_is64 = (nz == 0) ? 1 : 0;
}

__global__ void prep_kernel(const float* __restrict__ verts,
                            const void*  __restrict__ facesp,
                            const float* __restrict__ Km,
                            const float* __restrict__ Rm,
                            const float* __restrict__ tm,
                            const int*   __restrict__ oszp,
                            int NF, int NV)
{
    int f = blockIdx.x * blockDim.x + threadIdx.x;
    if (f >= NF) return;

    // robust orig_size read (int32 / int64-low-word / float32); nullptr -> 224
    float os = 224.0f;
    if (oszp) {
        int iv = oszp[0];
        if (iv > 0 && iv < 1000000) os = (float)iv;
        else {
            float fv = __int_as_float(iv);
            if (fv > 0.0f && fv < 1000000.0f) os = fv;
        }
    }

    const int is64 = g_is64;
    const long long* f64 = (const long long*)facesp;
    const int*       f32 = (const int*)facesp;

    float fx = Km[0], fy = Km[4], cx = Km[2], cy = Km[5];

    float x[3], y[3], z[3];
#pragma unroll
    for (int c = 0; c < 3; c++) {
        long long vi = is64 ? f64[f * 3 + c] : (long long)f32[f * 3 + c];
        if (vi < 0) vi = 0;
        if (vi >= NV) vi = NV - 1;
        float vx = verts[vi * 3 + 0];
        float vy = verts[vi * 3 + 1];
        float vz = verts[vi * 3 + 2];
        float X = Rm[0] * vx + Rm[1] * vy + Rm[2] * vz + tm[0];
        float Y = Rm[3] * vx + Rm[4] * vy + Rm[5] * vz + tm[1];
        float Z = Rm[6] * vx + Rm[7] * vy + Rm[8] * vz + tm[2];
        float u = fx * X + cx;
        float w = fy * Y + cy;
        x[c] = 2.0f * u / os - 1.0f;
        y[c] = -(2.0f * w / os - 1.0f);
        z[c] = Z;
    }

    float A0 = y[1] - y[2], B0 = x[2] - x[1], C0 = x[1] * y[2] - x[2] * y[1];
    float A1 = y[2] - y[0], B1 = x[0] - x[2], C1 = x[2] * y[0] - x[0] * y[2];
    float A2 = y[0] - y[1], B2 = x[1] - x[0], C2 = x[0] * y[1] - x[1] * y[0];
    float area = C0 + C1 + C2;

    if (fabsf(area) <= 1e-10f) {
        g_bb[f] = make_float4(2.0f, -2.0f, 2.0f, -2.0f);
        g_e0[f] = make_float4(0, 0, 0, 0);
        g_e1[f] = make_float4(0, 0, 0, 0);
        g_e2[f] = make_float4(0, 0, 0, 0);
        return;
    }

    float s = (area > 0.0f) ? 1.0f : -1.0f;
    A0 *= s; B0 *= s; C0 *= s;
    A1 *= s; B1 *= s; C1 *= s;
    A2 *= s; B2 *= s; C2 *= s;
    float inv = 1.0f / (s * area);

    float Pa = (A0 * z[0] + A1 * z[1] + A2 * z[2]) * inv;
    float Pb = (B0 * z[0] + B1 * z[1] + B2 * z[2]) * inv;
    float Pc = (C0 * z[0] + C1 * z[1] + C2 * z[2]) * inv;

    g_e0[f] = make_float4(A0, B0, C0, Pa);
    g_e1[f] = make_float4(A1, B1, C1, Pb);
    g_e2[f] = make_float4(A2, B2, C2, Pc);

    float4 bb;
    bb.x = fminf(x[0], fminf(x[1], x[2]));
    bb.y = fmaxf(x[0], fmaxf(x[1], x[2]));
    bb.z = fminf(y[0], fminf(y[1], y[2]));
    bb.w = fmaxf(y[0], fmaxf(y[1], y[2]));
    g_bb[f] = bb;
}

// grid: (256 tiles, NSLICE face-slices). block: 64 threads.
// thread j: tile row = j>>2 (0..15), 4 horizontally adjacent pixels (j&3)*4 .. +3
__global__ __launch_bounds__(RTHREADS)
void raster_kernel(int* __restrict__ outi, int NF)
{
    __shared__ float4 s_e0[CHUNK];
    __shared__ float4 s_e1[CHUNK];
    __shared__ float4 s_e2[CHUNK];
    __shared__ int    s_n;

    const int tileId = blockIdx.x;
    const int tx = tileId & (NTILEX - 1);
    const int ty = tileId >> 4;

    const int j    = threadIdx.x;
    const int row  = j >> 2;
    const int cg   = j & 3;
    const int gcol0 = tx * TILE + cg * 4;
    const int grow  = ty * TILE + row;

    const float scale = 2.0f / IS;
    const float px0 = (gcol0 + 0.5f) * scale - 1.0f;
    const float px1 = px0 + scale;
    const float px2 = px0 + 2.0f * scale;
    const float px3 = px0 + 3.0f * scale;
    const float py  = 1.0f - (grow + 0.5f) * scale;

    // tile extents in pixel-center coordinates
    const float pxlo = (tx * TILE + 0.5f) * scale - 1.0f;
    const float pxhi = (tx * TILE + TILE - 0.5f) * scale - 1.0f;
    const float pyhi = 1.0f - (ty * TILE + 0.5f) * scale;
    const float pylo = 1.0f - (ty * TILE + TILE - 0.5f) * scale;
    const float tcx = 0.5f * (pxlo + pxhi), thx = 0.5f * (pxhi - pxlo);
    const float tcy = 0.5f * (pylo + pyhi), thy = 0.5f * (pyhi - pylo);

    const int sliceLen = (NF + NSLICE - 1) / NSLICE;
    const int fstart = blockIdx.y * sliceLen;
    const int fend   = min(NF, fstart + sliceLen);

    float d0 = FARV, d1 = FARV, d2 = FARV, d3 = FARV;

    for (int base = fstart; base < fend; base += CHUNK) {
        if (j == 0) s_n = 0;
        __syncthreads();

        const int lim = min(base + CHUNK, fend);

        // cooperative filter: bbox + exact SAT (box axes via bbox, edge normals below)
#pragma unroll
        for (int off = 0; off < CHUNK; off += RTHREADS) {
            int f = base + off + j;
            bool pass = false;
            float4 e0, e1, e2;
            if (f < lim) {
                float4 bb = g_bb[f];
                if (bb.x <= pxhi && bb.y >= pxlo && bb.z <= pyhi && bb.w >= pylo) {
                    e0 = g_e0[f]; e1 = g_e1[f]; e2 = g_e2[f];
                    // max of edge fn over tile box; if < 0 the tile is fully outside
                    float w0m = fmaf(e0.x, tcx, fmaf(e0.y, tcy, e0.z)) +
                                fmaf(fabsf(e0.x), thx, fabsf(e0.y) * thy);
                    float w1m = fmaf(e1.x, tcx, fmaf(e1.y, tcy, e1.z)) +
                                fmaf(fabsf(e1.x), thx, fabsf(e1.y) * thy);
                    float w2m = fmaf(e2.x, tcx, fmaf(e2.y, tcy, e2.z)) +
                                fmaf(fabsf(e2.x), thx, fabsf(e2.y) * thy);
                    pass = (fminf(w0m, fminf(w1m, w2m)) >= -1e-6f);
                }
            }
            unsigned m = __ballot_sync(0xffffffffu, pass);
            int lane = j & 31;
            int posw = 0;
            int cnt = __popc(m);
            if (lane == 0 && cnt) posw = atomicAdd(&s_n, cnt);
            posw = __shfl_sync(0xffffffffu, posw, 0);
            if (pass) {
                int p = posw + __popc(m & ((1u << lane) - 1u));
                s_e0[p] = e0; s_e1[p] = e1; s_e2[p] = e2;
            }
        }
        __syncthreads();

        const int n = s_n;
#pragma unroll 2
        for (int i = 0; i < n; i++) {
            float4 e0 = s_e0[i];
            float4 e1 = s_e1[i];
            float4 e2 = s_e2[i];
            float b0 = fmaf(e0.y, py, e0.z);
            float b1 = fmaf(e1.y, py, e1.z);
            float b2 = fmaf(e2.y, py, e2.z);
            float bz = fmaf(e1.w, py, e2.w);

            {
                float w0 = fmaf(e0.x, px0, b0);
                float w1 = fmaf(e1.x, px0, b1);
                float w2 = fmaf(e2.x, px0, b2);
                float zp = fmaf(e0.w, px0, bz);
                float mn = fminf(w0, fminf(w1, w2));
                if (mn >= 0.0f && zp > NEARV) d0 = fminf(d0, zp);
            }
            {
                float w0 = fmaf(e0.x, px1, b0);
                float w1 = fmaf(e1.x, px1, b1);
                float w2 = fmaf(e2.x, px1, b2);
                float zp = fmaf(e0.w, px1, bz);
                float mn = fminf(w0, fminf(w1, w2));
                if (mn >= 0.0f && zp > NEARV) d1 = fminf(d1, zp);
            }
            {
                float w0 = fmaf(e0.x, px2, b0);
                float w1 = fmaf(e1.x, px2, b1);
                float w2 = fmaf(e2.x, px2, b2);
                float zp = fmaf(e0.w, px2, bz);
                float mn = fminf(w0, fminf(w1, w2));
                if (mn >= 0.0f && zp > NEARV) d2 = fminf(d2, zp);
            }
            {
                float w0 = fmaf(e0.x, px3, b0);
                float w1 = fmaf(e1.x, px3, b1);
                float w2 = fmaf(e2.x, px3, b2);
                float zp = fmaf(e0.w, px3, bz);
                float mn = fminf(w0, fminf(w1, w2));
                if (mn >= 0.0f && zp > NEARV) d3 = fminf(d3, zp);
            }
        }
        __syncthreads();
    }

    // positive floats: int compare == float compare
    int o = grow * IS + gcol0;
    atomicMin(&outi[o + 0], __float_as_int(d0));
    atomicMin(&outi[o + 1], __float_as_int(d1));
    atomicMin(&outi[o + 2], __float_as_int(d2));
    atomicMin(&outi[o + 3], __float_as_int(d3));
}

extern "C" void kernel_launch(void* const* d_in, const int* in_sizes, int n_in,
                              void* d_out, int out_size)
{
    const float* verts  = (const float*)d_in[0];
    const void*  facesp = d_in[1];
    const float* K      = (const float*)d_in[2];
    const float* R      = (const float*)d_in[3];
    const float* t      = (const float*)d_in[4];
    const int*   osz    = (n_in >= 6) ? (const int*)d_in[5] : nullptr;

    int NF = in_sizes[1] / 3;   // skip reversed-winding duplicates (identical coverage)
    if (NF > NF_MAX) NF = NF_MAX;
    int NV = in_sizes[0] / 3;

    int* outi = (int*)d_out;
    init_kernel<<<(out_size + 255) / 256, 256>>>(outi, out_size);
    detect_kernel<<<1, 1>>>((const int*)facesp, NF * 3);
    prep_kernel<<<(NF + 127) / 128, 128>>>(verts, facesp, K, R, t, osz, NF, NV);

    dim3 grid(NTILEX * NTILEX, NSLICE);
    raster_kernel<<<grid, RTHREADS>>>(outi, NF);
}

// round 3
// speedup vs baseline: 1.7704x; 1.7704x over previous
#include <cuda_runtime.h>

#define IS      256
#define TILE    16
#define NTILEX  (IS / TILE)          // 16
#define NSLICE  32
#define CHUNK   128
#define RTHREADS 64
#define NF_MAX  24000
#define FARV    100.0f
#define NEARV   0.1f

// Per-face preprocessed data (sign-premultiplied edge equations + depth plane + bbox).
// e0 = (A0, B0, C0, Pa)   w0 = A0*px + B0*py + C0
// e1 = (A1, B1, C1, Pb)
// e2 = (A2, B2, C2, Pc)   zp = Pa*px + Pb*py + Pc   (1/|area| folded in)
__device__ float4 g_e0[NF_MAX];
__device__ float4 g_e1[NF_MAX];
__device__ float4 g_e2[NF_MAX];
__device__ float4 g_bb[NF_MAX];

__global__ void init_kernel(int* __restrict__ outi, int n)
{
    int i = blockIdx.x * blockDim.x + threadIdx.x;
    if (i < n) outi[i] = __float_as_int(FARV);
}

__global__ void prep_kernel(const float* __restrict__ verts,
                            const void*  __restrict__ facesp,
                            const float* __restrict__ Km,
                            const float* __restrict__ Rm,
                            const float* __restrict__ tm,
                            const int*   __restrict__ oszp,
                            int NF, int NV)
{
    int f = blockIdx.x * blockDim.x + threadIdx.x;
    if (f >= NF) return;

    // robust orig_size read (int32 / int64-low-word / float32); nullptr -> 224
    float os = 224.0f;
    if (oszp) {
        int iv = oszp[0];
        if (iv > 0 && iv < 1000000) os = (float)iv;
        else {
            float fv = __int_as_float(iv);
            if (fv > 0.0f && fv < 1000000.0f) os = fv;
        }
    }

    // dtype sniff: int64 indices in [0,NV) have zero hi-words. All threads read
    // the same 8 odd words (L1 broadcast) -> globally consistent decision.
    const int* f32 = (const int*)facesp;
    int oddbits = 0;
#pragma unroll
    for (int i = 1; i < 16; i += 2) oddbits |= f32[i];
    const bool is64 = (oddbits == 0);
    const long long* f64 = (const long long*)facesp;

    float fx = Km[0], fy = Km[4], cx = Km[2], cy = Km[5];

    float x[3], y[3], z[3];
#pragma unroll
    for (int c = 0; c < 3; c++) {
        long long vi = is64 ? f64[f * 3 + c] : (long long)f32[f * 3 + c];
        if (vi < 0) vi = 0;
        if (vi >= NV) vi = NV - 1;
        float vx = verts[vi * 3 + 0];
        float vy = verts[vi * 3 + 1];
        float vz = verts[vi * 3 + 2];
        float X = Rm[0] * vx + Rm[1] * vy + Rm[2] * vz + tm[0];
        float Y = Rm[3] * vx + Rm[4] * vy + Rm[5] * vz + tm[1];
        float Z = Rm[6] * vx + Rm[7] * vy + Rm[8] * vz + tm[2];
        float u = fx * X + cx;
        float w = fy * Y + cy;
        x[c] = 2.0f * u / os - 1.0f;
        y[c] = -(2.0f * w / os - 1.0f);
        z[c] = Z;
    }

    float A0 = y[1] - y[2], B0 = x[2] - x[1], C0 = x[1] * y[2] - x[2] * y[1];
    float A1 = y[2] - y[0], B1 = x[0] - x[2], C1 = x[2] * y[0] - x[0] * y[2];
    float A2 = y[0] - y[1], B2 = x[1] - x[0], C2 = x[0] * y[1] - x[1] * y[0];
    float area = C0 + C1 + C2;

    if (fabsf(area) <= 1e-10f) {
        g_bb[f] = make_float4(2.0f, -2.0f, 2.0f, -2.0f);
        g_e0[f] = make_float4(0, 0, 0, 0);
        g_e1[f] = make_float4(0, 0, 0, 0);
        g_e2[f] = make_float4(0, 0, 0, 0);
        return;
    }

    float s = (area > 0.0f) ? 1.0f : -1.0f;
    A0 *= s; B0 *= s; C0 *= s;
    A1 *= s; B1 *= s; C1 *= s;
    A2 *= s; B2 *= s; C2 *= s;
    float inv = 1.0f / (s * area);

    float Pa = (A0 * z[0] + A1 * z[1] + A2 * z[2]) * inv;
    float Pb = (B0 * z[0] + B1 * z[1] + B2 * z[2]) * inv;
    float Pc = (C0 * z[0] + C1 * z[1] + C2 * z[2]) * inv;

    g_e0[f] = make_float4(A0, B0, C0, Pa);
    g_e1[f] = make_float4(A1, B1, C1, Pb);
    g_e2[f] = make_float4(A2, B2, C2, Pc);

    float4 bb;
    bb.x = fminf(x[0], fminf(x[1], x[2]));
    bb.y = fmaxf(x[0], fmaxf(x[1], x[2]));
    bb.z = fminf(y[0], fminf(y[1], y[2]));
    bb.w = fmaxf(y[0], fmaxf(y[1], y[2]));
    g_bb[f] = bb;
}

// grid: (256 tiles, NSLICE face-slices). block: 64 threads.
// thread j: tile row = j>>2 (0..15), 4 horizontally adjacent pixels (j&3)*4 .. +3
__global__ __launch_bounds__(RTHREADS)
void raster_kernel(int* __restrict__ outi, int NF)
{
    __shared__ float4 s_e0[CHUNK];
    __shared__ float4 s_e1[CHUNK];
    __shared__ float4 s_e2[CHUNK];
    __shared__ int    s_n;

    const int tileId = blockIdx.x;
    const int tx = tileId & (NTILEX - 1);
    const int ty = tileId >> 4;

    const int j    = threadIdx.x;
    const int row  = j >> 2;
    const int cg   = j & 3;
    const int gcol0 = tx * TILE + cg * 4;
    const int grow  = ty * TILE + row;

    const float scale = 2.0f / IS;
    const float px0 = (gcol0 + 0.5f) * scale - 1.0f;
    const float px1 = px0 + scale;
    const float px2 = px0 + 2.0f * scale;
    const float px3 = px0 + 3.0f * scale;
    const float py  = 1.0f - (grow + 0.5f) * scale;

    // tile extents in pixel-center coordinates
    const float pxlo = (tx * TILE + 0.5f) * scale - 1.0f;
    const float pxhi = (tx * TILE + TILE - 0.5f) * scale - 1.0f;
    const float pyhi = 1.0f - (ty * TILE + 0.5f) * scale;
    const float pylo = 1.0f - (ty * TILE + TILE - 0.5f) * scale;
    const float tcx = 0.5f * (pxlo + pxhi), thx = 0.5f * (pxhi - pxlo);
    const float tcy = 0.5f * (pylo + pyhi), thy = 0.5f * (pyhi - pylo);

    const int sliceLen = (NF + NSLICE - 1) / NSLICE;
    const int fstart = blockIdx.y * sliceLen;
    const int fend   = min(NF, fstart + sliceLen);

    // accumulate min of (zp - NEARV); recovered at the end
    float d0 = FARV, d1 = FARV, d2 = FARV, d3 = FARV;

    for (int base = fstart; base < fend; base += CHUNK) {
        if (j == 0) s_n = 0;
        __syncthreads();

        const int lim = min(base + CHUNK, fend);

        // cooperative filter: bbox + exact SAT (box axes via bbox, edge normals below)
#pragma unroll
        for (int off = 0; off < CHUNK; off += RTHREADS) {
            int f = base + off + j;
            bool pass = false;
            float4 e0, e1, e2;
            if (f < lim) {
                float4 bb = g_bb[f];
                if (bb.x <= pxhi && bb.y >= pxlo && bb.z <= pyhi && bb.w >= pylo) {
                    e0 = g_e0[f]; e1 = g_e1[f]; e2 = g_e2[f];
                    // max of edge fn over tile box; if < 0 the tile is fully outside
                    float w0m = fmaf(e0.x, tcx, fmaf(e0.y, tcy, e0.z)) +
                                fmaf(fabsf(e0.x), thx, fabsf(e0.y) * thy);
                    float w1m = fmaf(e1.x, tcx, fmaf(e1.y, tcy, e1.z)) +
                                fmaf(fabsf(e1.x), thx, fabsf(e1.y) * thy);
                    float w2m = fmaf(e2.x, tcx, fmaf(e2.y, tcy, e2.z)) +
                                fmaf(fabsf(e2.x), thx, fabsf(e2.y) * thy);
                    pass = (fminf(w0m, fminf(w1m, w2m)) >= -1e-6f);
                }
            }
            unsigned m = __ballot_sync(0xffffffffu, pass);
            int lane = j & 31;
            int posw = 0;
            int cnt = __popc(m);
            if (lane == 0 && cnt) posw = atomicAdd(&s_n, cnt);
            posw = __shfl_sync(0xffffffffu, posw, 0);
            if (pass) {
                int p = posw + __popc(m & ((1u << lane) - 1u));
                s_e0[p] = e0; s_e1[p] = e1; s_e2[p] = e2;
            }
        }
        __syncthreads();

        const int n = s_n;
#pragma unroll 2
        for (int i = 0; i < n; i++) {
            float4 e0 = s_e0[i];
            float4 e1 = s_e1[i];
            float4 e2 = s_e2[i];
            float b0 = fmaf(e0.y, py, e0.z);
            float b1 = fmaf(e1.y, py, e1.z);
            float b2 = fmaf(e2.y, py, e2.z);
            float bz = fmaf(e1.w, py, e2.w) - NEARV;   // fold near-test

            {
                float w0 = fmaf(e0.x, px0, b0);
                float w1 = fmaf(e1.x, px0, b1);
                float w2 = fmaf(e2.x, px0, b2);
                float zn = fmaf(e0.w, px0, bz);
                float mn = fminf(fminf(w0, w1), fminf(w2, zn));
                if (mn >= 0.0f) d0 = fminf(d0, zn);
            }
            {
                float w0 = fmaf(e0.x, px1, b0);
                float w1 = fmaf(e1.x, px1, b1);
                float w2 = fmaf(e2.x, px1, b2);
                float zn = fmaf(e0.w, px1, bz);
                float mn = fminf(fminf(w0, w1), fminf(w2, zn));
                if (mn >= 0.0f) d1 = fminf(d1, zn);
            }
            {
                float w0 = fmaf(e0.x, px2, b0);
                float w1 = fmaf(e1.x, px2, b1);
                float w2 = fmaf(e2.x, px2, b2);
                float zn = fmaf(e0.w, px2, bz);
                float mn = fminf(fminf(w0, w1), fminf(w2, zn));
                if (mn >= 0.0f) d2 = fminf(d2, zn);
            }
            {
                float w0 = fmaf(e0.x, px3, b0);
                float w1 = fmaf(e1.x, px3, b1);
                float w2 = fmaf(e2.x, px3, b2);
                float zn = fmaf(e0.w, px3, bz);
                float mn = fminf(fminf(w0, w1), fminf(w2, zn));
                if (mn >= 0.0f) d3 = fminf(d3, zn);
            }
        }
        __syncthreads();
    }

    // restore zp = zn + NEARV (cap at FARV), positive floats: int cmp == float cmp
    d0 = fminf(d0 + NEARV, FARV);
    d1 = fminf(d1 + NEARV, FARV);
    d2 = fminf(d2 + NEARV, FARV);
    d3 = fminf(d3 + NEARV, FARV);
    int o = grow * IS + gcol0;
    atomicMin(&outi[o + 0], __float_as_int(d0));
    atomicMin(&outi[o + 1], __float_as_int(d1));
    atomicMin(&outi[o + 2], __float_as_int(d2));
    atomicMin(&outi[o + 3], __float_as_int(d3));
}

extern "C" void kernel_launch(void* const* d_in, const int* in_sizes, int n_in,
                              void* d_out, int out_size)
{
    const float* verts  = (const float*)d_in[0];
    const void*  facesp = d_in[1];
    const float* K      = (const float*)d_in[2];
    const float* R      = (const float*)d_in[3];
    const float* t      = (const float*)d_in[4];
    const int*   osz    = (n_in >= 6) ? (const int*)d_in[5] : nullptr;

    int NF = in_sizes[1] / 3;   // skip reversed-winding duplicates (identical coverage)
    if (NF > NF_MAX) NF = NF_MAX;
    int NV = in_sizes[0] / 3;

    int* outi = (int*)d_out;
    init_kernel<<<(out_size + 255) / 256, 256>>>(outi, out_size);
    prep_kernel<<<(NF + 127) / 128, 128>>>(verts, facesp, K, R, t, osz, NF, NV);

    dim3 grid(NTILEX * NTILEX, NSLICE);
    raster_kernel<<<grid, RTHREADS>>>(outi, NF);
}

// round 4
// speedup vs baseline: 2.4807x; 1.4012x over previous
#include <cuda_runtime.h>

#define IS      256
#define TILE    16
#define NTILEX  (IS / TILE)          // 16
#define NSLICE  16
#define CHUNK   128
#define RTHREADS 64
#define NF_MAX  24000
#define FARV    100.0f
#define NEARV   0.1f

// Per-face preprocessed data (sign-premultiplied edge equations + depth plane + bbox).
// e0 = (A0, B0, C0, Pa)   w0 = A0*px + B0*py + C0
// e1 = (A1, B1, C1, Pb)
// e2 = (A2, B2, C2, Pc)   zp = Pa*px + Pb*py + Pc   (1/|area| folded in)
// zp4 = (Pa, Pb, Pc, 0)   for the cheap tile z-min test
__device__ float4 g_e0[NF_MAX];
__device__ float4 g_e1[NF_MAX];
__device__ float4 g_e2[NF_MAX];
__device__ float4 g_bb[NF_MAX];
__device__ float4 g_zp[NF_MAX];

__global__ void init_kernel(int* __restrict__ outi, int n)
{
    int i = blockIdx.x * blockDim.x + threadIdx.x;
    if (i < n) outi[i] = __float_as_int(FARV);
}

__global__ void prep_kernel(const float* __restrict__ verts,
                            const void*  __restrict__ facesp,
                            const float* __restrict__ Km,
                            const float* __restrict__ Rm,
                            const float* __restrict__ tm,
                            const int*   __restrict__ oszp,
                            int NF, int NV)
{
    int f = blockIdx.x * blockDim.x + threadIdx.x;
    if (f >= NF) return;

    // robust orig_size read (int32 / int64-low-word / float32); nullptr -> 224
    float os = 224.0f;
    if (oszp) {
        int iv = oszp[0];
        if (iv > 0 && iv < 1000000) os = (float)iv;
        else {
            float fv = __int_as_float(iv);
            if (fv > 0.0f && fv < 1000000.0f) os = fv;
        }
    }

    // dtype sniff: int64 indices in [0,NV) have zero hi-words. All threads read
    // the same 8 odd words (L1 broadcast) -> globally consistent decision.
    const int* f32 = (const int*)facesp;
    int oddbits = 0;
#pragma unroll
    for (int i = 1; i < 16; i += 2) oddbits |= f32[i];
    const bool is64 = (oddbits == 0);
    const long long* f64 = (const long long*)facesp;

    float fx = Km[0], fy = Km[4], cx = Km[2], cy = Km[5];

    float x[3], y[3], z[3];
#pragma unroll
    for (int c = 0; c < 3; c++) {
        long long vi = is64 ? f64[f * 3 + c] : (long long)f32[f * 3 + c];
        if (vi < 0) vi = 0;
        if (vi >= NV) vi = NV - 1;
        float vx = verts[vi * 3 + 0];
        float vy = verts[vi * 3 + 1];
        float vz = verts[vi * 3 + 2];
        float X = Rm[0] * vx + Rm[1] * vy + Rm[2] * vz + tm[0];
        float Y = Rm[3] * vx + Rm[4] * vy + Rm[5] * vz + tm[1];
        float Z = Rm[6] * vx + Rm[7] * vy + Rm[8] * vz + tm[2];
        float u = fx * X + cx;
        float w = fy * Y + cy;
        x[c] = 2.0f * u / os - 1.0f;
        y[c] = -(2.0f * w / os - 1.0f);
        z[c] = Z;
    }

    float A0 = y[1] - y[2], B0 = x[2] - x[1], C0 = x[1] * y[2] - x[2] * y[1];
    float A1 = y[2] - y[0], B1 = x[0] - x[2], C1 = x[2] * y[0] - x[0] * y[2];
    float A2 = y[0] - y[1], B2 = x[1] - x[0], C2 = x[0] * y[1] - x[1] * y[0];
    float area = C0 + C1 + C2;

    if (fabsf(area) <= 1e-10f) {
        g_bb[f] = make_float4(2.0f, -2.0f, 2.0f, -2.0f);
        g_e0[f] = make_float4(0, 0, 0, 0);
        g_e1[f] = make_float4(0, 0, 0, 0);
        g_e2[f] = make_float4(0, 0, 0, 0);
        g_zp[f] = make_float4(0, 0, 0, 0);
        return;
    }

    float s = (area > 0.0f) ? 1.0f : -1.0f;
    A0 *= s; B0 *= s; C0 *= s;
    A1 *= s; B1 *= s; C1 *= s;
    A2 *= s; B2 *= s; C2 *= s;
    float inv = 1.0f / (s * area);

    float Pa = (A0 * z[0] + A1 * z[1] + A2 * z[2]) * inv;
    float Pb = (B0 * z[0] + B1 * z[1] + B2 * z[2]) * inv;
    float Pc = (C0 * z[0] + C1 * z[1] + C2 * z[2]) * inv;

    g_e0[f] = make_float4(A0, B0, C0, Pa);
    g_e1[f] = make_float4(A1, B1, C1, Pb);
    g_e2[f] = make_float4(A2, B2, C2, Pc);
    g_zp[f] = make_float4(Pa, Pb, Pc, 0.0f);

    float4 bb;
    bb.x = fminf(x[0], fminf(x[1], x[2]));
    bb.y = fmaxf(x[0], fmaxf(x[1], x[2]));
    bb.z = fminf(y[0], fminf(y[1], y[2]));
    bb.w = fmaxf(y[0], fmaxf(y[1], y[2]));
    g_bb[f] = bb;
}

// grid: (256 tiles, NSLICE face-slices). block: 64 threads.
// thread j: tile row = j>>2 (0..15), 4 horizontally adjacent pixels (j&3)*4 .. +3
__global__ __launch_bounds__(RTHREADS)
void raster_kernel(int* __restrict__ outi, int NF)
{
    __shared__ float4 s_e0[CHUNK];
    __shared__ float4 s_e1[CHUNK];
    __shared__ float4 s_e2[CHUNK];
    __shared__ int    s_n;
    __shared__ float  s_B;
    __shared__ float  s_wmax[2];

    const int tileId = blockIdx.x;
    const int tx = tileId & (NTILEX - 1);
    const int ty = tileId >> 4;

    const int j    = threadIdx.x;
    const int row  = j >> 2;
    const int cg   = j & 3;
    const int gcol0 = tx * TILE + cg * 4;
    const int grow  = ty * TILE + row;

    const float scale = 2.0f / IS;
    const float px0 = (gcol0 + 0.5f) * scale - 1.0f;
    const float px1 = px0 + scale;
    const float px2 = px0 + 2.0f * scale;
    const float px3 = px0 + 3.0f * scale;
    const float py  = 1.0f - (grow + 0.5f) * scale;

    // tile extents in pixel-center coordinates
    const float pxlo = (tx * TILE + 0.5f) * scale - 1.0f;
    const float pxhi = (tx * TILE + TILE - 0.5f) * scale - 1.0f;
    const float pyhi = 1.0f - (ty * TILE + 0.5f) * scale;
    const float pylo = 1.0f - (ty * TILE + TILE - 0.5f) * scale;
    const float tcx = 0.5f * (pxlo + pxhi), thx = 0.5f * (pxhi - pxlo);
    const float tcy = 0.5f * (pylo + pyhi), thy = 0.5f * (pyhi - pylo);

    const int sliceLen = (NF + NSLICE - 1) / NSLICE;
    const int fstart = blockIdx.y * sliceLen;
    const int fend   = min(NF, fstart + sliceLen);

    if (j < 2) s_wmax[j] = FARV;
    if (j == 0) s_B = FARV;

    // accumulate min of (zp - NEARV); recovered at the end
    float d0 = FARV, d1 = FARV, d2 = FARV, d3 = FARV;

    for (int base = fstart; base < fend; base += CHUNK) {
        if (j == 0) {
            s_n = 0;
            s_B = fminf(s_B, fmaxf(s_wmax[0], s_wmax[1]));
        }
        __syncthreads();
        const float B = s_B + 1e-5f;   // conservative slack vs FP re-expression

        const int lim = min(base + CHUNK, fend);

        // cooperative filter: bbox -> tile z-min vs depth bound -> exact SAT
#pragma unroll
        for (int off = 0; off < CHUNK; off += RTHREADS) {
            int f = base + off + j;
            bool pass = false;
            float4 e0, e1, e2;
            if (f < lim) {
                float4 bb = g_bb[f];
                if (bb.x <= pxhi && bb.y >= pxlo && bb.z <= pyhi && bb.w >= pylo) {
                    float4 zp4 = g_zp[f];
                    // min of depth plane over the tile box, in zn (= zp-NEAR) units
                    float zc  = fmaf(zp4.x, tcx, fmaf(zp4.y, tcy, zp4.z));
                    float zmn = zc - fmaf(fabsf(zp4.x), thx, fabsf(zp4.y) * thy) - NEARV;
                    if (zmn <= B) {
                        e0 = g_e0[f]; e1 = g_e1[f]; e2 = g_e2[f];
                        // max of edge fn over tile box; if < 0 the tile is fully outside
                        float w0m = fmaf(e0.x, tcx, fmaf(e0.y, tcy, e0.z)) +
                                    fmaf(fabsf(e0.x), thx, fabsf(e0.y) * thy);
                        float w1m = fmaf(e1.x, tcx, fmaf(e1.y, tcy, e1.z)) +
                                    fmaf(fabsf(e1.x), thx, fabsf(e1.y) * thy);
                        float w2m = fmaf(e2.x, tcx, fmaf(e2.y, tcy, e2.z)) +
                                    fmaf(fabsf(e2.x), thx, fabsf(e2.y) * thy);
                        pass = (fminf(w0m, fminf(w1m, w2m)) >= -1e-6f);
                    }
                }
            }
            unsigned m = __ballot_sync(0xffffffffu, pass);
            int lane = j & 31;
            int posw = 0;
            int cnt = __popc(m);
            if (lane == 0 && cnt) posw = atomicAdd(&s_n, cnt);
            posw = __shfl_sync(0xffffffffu, posw, 0);
            if (pass) {
                int p = posw + __popc(m & ((1u << lane) - 1u));
                s_e0[p] = e0; s_e1[p] = e1; s_e2[p] = e2;
            }
        }
        __syncthreads();

        const int n = s_n;
#pragma unroll 2
        for (int i = 0; i < n; i++) {
            float4 e0 = s_e0[i];
            float4 e1 = s_e1[i];
            float4 e2 = s_e2[i];
            float b0 = fmaf(e0.y, py, e0.z);
            float b1 = fmaf(e1.y, py, e1.z);
            float b2 = fmaf(e2.y, py, e2.z);
            float bz = fmaf(e1.w, py, e2.w) - NEARV;   // fold near-test

            {
                float w0 = fmaf(e0.x, px0, b0);
                float w1 = fmaf(e1.x, px0, b1);
                float w2 = fmaf(e2.x, px0, b2);
                float zn = fmaf(e0.w, px0, bz);
                float mn = fminf(fminf(w0, w1), fminf(w2, zn));
                if (mn >= 0.0f) d0 = fminf(d0, zn);
            }
            {
                float w0 = fmaf(e0.x, px1, b0);
                float w1 = fmaf(e1.x, px1, b1);
                float w2 = fmaf(e2.x, px1, b2);
                float zn = fmaf(e0.w, px1, bz);
                float mn = fminf(fminf(w0, w1), fminf(w2, zn));
                if (mn >= 0.0f) d1 = fminf(d1, zn);
            }
            {
                float w0 = fmaf(e0.x, px2, b0);
                float w1 = fmaf(e1.x, px2, b1);
                float w2 = fmaf(e2.x, px2, b2);
                float zn = fmaf(e0.w, px2, bz);
                float mn = fminf(fminf(w0, w1), fminf(w2, zn));
                if (mn >= 0.0f) d2 = fminf(d2, zn);
            }
            {
                float w0 = fmaf(e0.x, px3, b0);
                float w1 = fmaf(e1.x, px3, b1);
                float w2 = fmaf(e2.x, px3, b2);
                float zn = fmaf(e0.w, px3, bz);
                float mn = fminf(fminf(w0, w1), fminf(w2, zn));
                if (mn >= 0.0f) d3 = fminf(d3, zn);
            }
        }

        // update tile depth bound: B = max over block pixels of running min
        float mx = fmaxf(fmaxf(d0, d1), fmaxf(d2, d3));
#pragma unroll
        for (int o = 16; o; o >>= 1)
            mx = fmaxf(mx, __shfl_xor_sync(0xffffffffu, mx, o));
        if ((j & 31) == 0) s_wmax[j >> 5] = mx;
        __syncthreads();
    }

    // restore zp = zn + NEARV (cap at FARV), positive floats: int cmp == float cmp
    d0 = fminf(d0 + NEARV, FARV);
    d1 = fminf(d1 + NEARV, FARV);
    d2 = fminf(d2 + NEARV, FARV);
    d3 = fminf(d3 + NEARV, FARV);
    int o = grow * IS + gcol0;
    atomicMin(&outi[o + 0], __float_as_int(d0));
    atomicMin(&outi[o + 1], __float_as_int(d1));
    atomicMin(&outi[o + 2], __float_as_int(d2));
    atomicMin(&outi[o + 3], __float_as_int(d3));
}

extern "C" void kernel_launch(void* const* d_in, const int* in_sizes, int n_in,
                              void* d_out, int out_size)
{
    const float* verts  = (const float*)d_in[0];
    const void*  facesp = d_in[1];
    const float* K      = (const float*)d_in[2];
    const float* R      = (const float*)d_in[3];
    const float* t      = (const float*)d_in[4];
    const int*   osz    = (n_in >= 6) ? (const int*)d_in[5] : nullptr;

    int NF = in_sizes[1] / 3;   // skip reversed-winding duplicates (identical coverage)
    if (NF > NF_MAX) NF = NF_MAX;
    int NV = in_sizes[0] / 3;

    int* outi = (int*)d_out;
    init_kernel<<<(out_size + 255) / 256, 256>>>(outi, out_size);
    prep_kernel<<<(NF + 127) / 128, 128>>>(verts, facesp, K, R, t, osz, NF, NV);

    dim3 grid(NTILEX * NTILEX, NSLICE);
    raster_kernel<<<grid, RTHREADS>>>(outi, NF);
}

// round 5
// speedup vs baseline: 2.6417x; 1.0649x over previous
#include <cuda_runtime.h>

#define IS      256
#define TILE    16
#define NTILEX  (IS / TILE)          // 16
#define NTILES  (NTILEX * NTILEX)    // 256
#define NSLICE  16
#define CHUNK   128
#define RTHREADS 64
#define NF_MAX  24000
#define NBINS   256
#define KRANGE  1.6f                 // key quantization range in zn units
#define FARV    100.0f
#define NEARV   0.1f

// unsorted (prep output) and depth-sorted (scatter output) face data
__device__ float4 u_e0[NF_MAX], u_e1[NF_MAX], u_e2[NF_MAX], u_bb[NF_MAX], u_zp[NF_MAX];
__device__ int    u_bin[NF_MAX];
__device__ float4 g_e0[NF_MAX], g_e1[NF_MAX], g_e2[NF_MAX], g_bb[NF_MAX], g_zp[NF_MAX];
__device__ float  g_key[NF_MAX];     // monotone bucket-floor of zn_min
__device__ int    g_hist[NBINS];
__device__ int    g_start[NBINS];
__device__ int    g_B[NTILES];       // per-tile depth bound (float bits, atomicMin)

__global__ void init_kernel(int* __restrict__ outi, int n)
{
    int i = blockIdx.x * blockDim.x + threadIdx.x;
    if (i < n) outi[i] = __float_as_int(FARV);
    if (i < NBINS)  g_hist[i] = 0;
    if (i < NTILES) g_B[i] = __float_as_int(FARV);
}

__global__ void prep_kernel(const float* __restrict__ verts,
                            const void*  __restrict__ facesp,
                            const float* __restrict__ Km,
                            const float* __restrict__ Rm,
                            const float* __restrict__ tm,
                            const int*   __restrict__ oszp,
                            int NF, int NV)
{
    int f = blockIdx.x * blockDim.x + threadIdx.x;
    if (f >= NF) return;

    // robust orig_size read (int32 / int64-low-word / float32); nullptr -> 224
    float os = 224.0f;
    if (oszp) {
        int iv = oszp[0];
        if (iv > 0 && iv < 1000000) os = (float)iv;
        else {
            float fv = __int_as_float(iv);
            if (fv > 0.0f && fv < 1000000.0f) os = fv;
        }
    }

    // dtype sniff: int64 indices in [0,NV) have zero hi-words (L1 broadcast reads)
    const int* f32 = (const int*)facesp;
    int oddbits = 0;
#pragma unroll
    for (int i = 1; i < 16; i += 2) oddbits |= f32[i];
    const bool is64 = (oddbits == 0);
    const long long* f64 = (const long long*)facesp;

    float fx = Km[0], fy = Km[4], cx = Km[2], cy = Km[5];

    float x[3], y[3], z[3];
#pragma unroll
    for (int c = 0; c < 3; c++) {
        long long vi = is64 ? f64[f * 3 + c] : (long long)f32[f * 3 + c];
        if (vi < 0) vi = 0;
        if (vi >= NV) vi = NV - 1;
        float vx = verts[vi * 3 + 0];
        float vy = verts[vi * 3 + 1];
        float vz = verts[vi * 3 + 2];
        float X = Rm[0] * vx + Rm[1] * vy + Rm[2] * vz + tm[0];
        float Y = Rm[3] * vx + Rm[4] * vy + Rm[5] * vz + tm[1];
        float Z = Rm[6] * vx + Rm[7] * vy + Rm[8] * vz + tm[2];
        float u = fx * X + cx;
        float w = fy * Y + cy;
        x[c] = 2.0f * u / os - 1.0f;
        y[c] = -(2.0f * w / os - 1.0f);
        z[c] = Z;
    }

    float A0 = y[1] - y[2], B0 = x[2] - x[1], C0 = x[1] * y[2] - x[2] * y[1];
    float A1 = y[2] - y[0], B1 = x[0] - x[2], C1 = x[2] * y[0] - x[0] * y[2];
    float A2 = y[0] - y[1], B2 = x[1] - x[0], C2 = x[0] * y[1] - x[1] * y[0];
    float area = C0 + C1 + C2;

    if (fabsf(area) <= 1e-10f) {
        u_bb[f] = make_float4(2.0f, -2.0f, 2.0f, -2.0f);
        u_e0[f] = make_float4(0, 0, 0, 0);
        u_e1[f] = make_float4(0, 0, 0, 0);
        u_e2[f] = make_float4(0, 0, 0, 0);
        u_zp[f] = make_float4(0, 0, 0, 0);
        u_bin[f] = NBINS - 1;
        atomicAdd(&g_hist[NBINS - 1], 1);
        return;
    }

    float s = (area > 0.0f) ? 1.0f : -1.0f;
    A0 *= s; B0 *= s; C0 *= s;
    A1 *= s; B1 *= s; C1 *= s;
    A2 *= s; B2 *= s; C2 *= s;
    float inv = 1.0f / (s * area);

    float Pa = (A0 * z[0] + A1 * z[1] + A2 * z[2]) * inv;
    float Pb = (B0 * z[0] + B1 * z[1] + B2 * z[2]) * inv;
    float Pc = (C0 * z[0] + C1 * z[1] + C2 * z[2]) * inv;

    u_e0[f] = make_float4(A0, B0, C0, Pa);
    u_e1[f] = make_float4(A1, B1, C1, Pb);
    u_e2[f] = make_float4(A2, B2, C2, Pc);
    u_zp[f] = make_float4(Pa, Pb, Pc, 0.0f);

    float4 bb;
    bb.x = fminf(x[0], fminf(x[1], x[2]));
    bb.y = fmaxf(x[0], fmaxf(x[1], x[2]));
    bb.z = fminf(y[0], fminf(y[1], y[2]));
    bb.w = fmaxf(y[0], fmaxf(y[1], y[2]));
    u_bb[f] = bb;

    float znmin = fminf(z[0], fminf(z[1], z[2])) - NEARV;
    int bin = (int)(znmin * (NBINS / KRANGE));
    bin = max(0, min(NBINS - 1, bin));
    u_bin[f] = bin;
    atomicAdd(&g_hist[bin], 1);
}

__global__ void prefix_kernel()
{
    __shared__ int tmp[NBINS];
    int t = threadIdx.x;
    int h = g_hist[t];
    tmp[t] = h;
    __syncthreads();
#pragma unroll
    for (int off = 1; off < NBINS; off <<= 1) {
        int v = (t >= off) ? tmp[t - off] : 0;
        __syncthreads();
        tmp[t] += v;
        __syncthreads();
    }
    g_start[t] = tmp[t] - h;   // exclusive prefix
}

__global__ void scatter_kernel(int NF)
{
    int f = blockIdx.x * blockDim.x + threadIdx.x;
    if (f >= NF) return;
    int bin = u_bin[f];
    int pos = atomicAdd(&g_start[bin], 1);
    g_e0[pos] = u_e0[f];
    g_e1[pos] = u_e1[f];
    g_e2[pos] = u_e2[f];
    g_bb[pos] = u_bb[f];
    g_zp[pos] = u_zp[f];
    g_key[pos] = bin * (KRANGE / NBINS);   // monotone bucket floor
}

// grid: (256 tiles, NSLICE). block: 64 threads.
// slice s handles chunks s, s+NSLICE, s+2*NSLICE, ... of the depth-sorted stream
__global__ __launch_bounds__(RTHREADS)
void raster_kernel(int* __restrict__ outi, int NF)
{
    __shared__ float4 s_e0[CHUNK];
    __shared__ float4 s_e1[CHUNK];
    __shared__ float4 s_e2[CHUNK];
    __shared__ int    s_n;
    __shared__ float  s_B;     // best local bound so far
    __shared__ float  s_Bm;    // merged (local, global) bound for this chunk
    __shared__ float  s_wmax[2];

    const int tileId = blockIdx.x;
    const int tx = tileId & (NTILEX - 1);
    const int ty = tileId >> 4;

    const int j    = threadIdx.x;
    const int row  = j >> 2;
    const int cg   = j & 3;
    const int gcol0 = tx * TILE + cg * 4;
    const int grow  = ty * TILE + row;

    const float scale = 2.0f / IS;
    const float px0 = (gcol0 + 0.5f) * scale - 1.0f;
    const float px1 = px0 + scale;
    const float px2 = px0 + 2.0f * scale;
    const float px3 = px0 + 3.0f * scale;
    const float py  = 1.0f - (grow + 0.5f) * scale;

    const float pxlo = (tx * TILE + 0.5f) * scale - 1.0f;
    const float pxhi = (tx * TILE + TILE - 0.5f) * scale - 1.0f;
    const float pyhi = 1.0f - (ty * TILE + 0.5f) * scale;
    const float pylo = 1.0f - (ty * TILE + TILE - 0.5f) * scale;
    const float tcx = 0.5f * (pxlo + pxhi), thx = 0.5f * (pxhi - pxlo);
    const float tcy = 0.5f * (pylo + pyhi), thy = 0.5f * (pyhi - pylo);

    if (j < 2) s_wmax[j] = FARV;
    if (j == 0) s_B = FARV;

    // accumulate min of zn = (zp - NEARV); restored at the end
    float d0 = FARV, d1 = FARV, d2 = FARV, d3 = FARV;

    for (int base = blockIdx.y * CHUNK; base < NF; base += NSLICE * CHUNK) {
        if (j == 0) {
            s_n = 0;
            float lb = fminf(s_B, fmaxf(s_wmax[0], s_wmax[1]));
            s_B = lb;
            s_Bm = fminf(lb, __int_as_float(g_B[tileId]));
        }
        __syncthreads();
        const float B = s_Bm + 1e-5f;   // conservative slack vs FP re-expression

        // sorted stream: all remaining faces have zn_min >= g_key[base]
        if (g_key[base] > B) break;

        const int lim = min(base + CHUNK, NF);

        // cooperative filter: bbox -> tile z-min vs depth bound -> exact SAT
#pragma unroll
        for (int off = 0; off < CHUNK; off += RTHREADS) {
            int f = base + off + j;
            bool pass = false;
            float4 e0, e1, e2;
            if (f < lim) {
                float4 bb = g_bb[f];
                if (bb.x <= pxhi && bb.y >= pxlo && bb.z <= pyhi && bb.w >= pylo) {
                    float4 zp4 = g_zp[f];
                    float zc  = fmaf(zp4.x, tcx, fmaf(zp4.y, tcy, zp4.z));
                    float zmn = zc - fmaf(fabsf(zp4.x), thx, fabsf(zp4.y) * thy) - NEARV;
                    if (zmn <= B) {
                        e0 = g_e0[f]; e1 = g_e1[f]; e2 = g_e2[f];
                        float w0m = fmaf(e0.x, tcx, fmaf(e0.y, tcy, e0.z)) +
                                    fmaf(fabsf(e0.x), thx, fabsf(e0.y) * thy);
                        float w1m = fmaf(e1.x, tcx, fmaf(e1.y, tcy, e1.z)) +
                                    fmaf(fabsf(e1.x), thx, fabsf(e1.y) * thy);
                        float w2m = fmaf(e2.x, tcx, fmaf(e2.y, tcy, e2.z)) +
                                    fmaf(fabsf(e2.x), thx, fabsf(e2.y) * thy);
                        pass = (fminf(w0m, fminf(w1m, w2m)) >= -1e-6f);
                    }
                }
            }
            unsigned m = __ballot_sync(0xffffffffu, pass);
            int lane = j & 31;
            int posw = 0;
            int cnt = __popc(m);
            if (lane == 0 && cnt) posw = atomicAdd(&s_n, cnt);
            posw = __shfl_sync(0xffffffffu, posw, 0);
            if (pass) {
                int p = posw + __popc(m & ((1u << lane) - 1u));
                s_e0[p] = e0; s_e1[p] = e1; s_e2[p] = e2;
            }
        }
        __syncthreads();

        const int n = s_n;
#pragma unroll 2
        for (int i = 0; i < n; i++) {
            float4 e0 = s_e0[i];
            float4 e1 = s_e1[i];
            float4 e2 = s_e2[i];
            float b0 = fmaf(e0.y, py, e0.z);
            float b1 = fmaf(e1.y, py, e1.z);
            float b2 = fmaf(e2.y, py, e2.z);
            float bz = fmaf(e1.w, py, e2.w) - NEARV;

            {
                float w0 = fmaf(e0.x, px0, b0);
                float w1 = fmaf(e1.x, px0, b1);
                float w2 = fmaf(e2.x, px0, b2);
                float zn = fmaf(e0.w, px0, bz);
                float mn = fminf(fminf(w0, w1), fminf(w2, zn));
                if (mn >= 0.0f) d0 = fminf(d0, zn);
            }
            {
                float w0 = fmaf(e0.x, px1, b0);
                float w1 = fmaf(e1.x, px1, b1);
                float w2 = fmaf(e2.x, px1, b2);
                float zn = fmaf(e0.w, px1, bz);
                float mn = fminf(fminf(w0, w1), fminf(w2, zn));
                if (mn >= 0.0f) d1 = fminf(d1, zn);
            }
            {
                float w0 = fmaf(e0.x, px2, b0);
                float w1 = fmaf(e1.x, px2, b1);
                float w2 = fmaf(e2.x, px2, b2);
                float zn = fmaf(e0.w, px2, bz);
                float mn = fminf(fminf(w0, w1), fminf(w2, zn));
                if (mn >= 0.0f) d2 = fminf(d2, zn);
            }
            {
                float w0 = fmaf(e0.x, px3, b0);
                float w1 = fmaf(e1.x, px3, b1);
                float w2 = fmaf(e2.x, px3, b2);
                float zn = fmaf(e0.w, px3, bz);
                float mn = fminf(fminf(w0, w1), fminf(w2, zn));
                if (mn >= 0.0f) d3 = fminf(d3, zn);
            }
        }

        // update + publish tile depth bound
        float mx = fmaxf(fmaxf(d0, d1), fmaxf(d2, d3));
#pragma unroll
        for (int o = 16; o; o >>= 1)
            mx = fmaxf(mx, __shfl_xor_sync(0xffffffffu, mx, o));
        if ((j & 31) == 0) s_wmax[j >> 5] = mx;
        __syncthreads();
        if (j == 0) {
            float nb = fminf(s_B, fmaxf(s_wmax[0], s_wmax[1]));
            s_B = nb;
            atomicMin(&g_B[tileId], __float_as_int(nb));  // positive floats: int==float order
        }
    }

    d0 = fminf(d0 + NEARV, FARV);
    d1 = fminf(d1 + NEARV, FARV);
    d2 = fminf(d2 + NEARV, FARV);
    d3 = fminf(d3 + NEARV, FARV);
    int o = grow * IS + gcol0;
    atomicMin(&outi[o + 0], __float_as_int(d0));
    atomicMin(&outi[o + 1], __float_as_int(d1));
    atomicMin(&outi[o + 2], __float_as_int(d2));
    atomicMin(&outi[o + 3], __float_as_int(d3));
}

extern "C" void kernel_launch(void* const* d_in, const int* in_sizes, int n_in,
                              void* d_out, int out_size)
{
    const float* verts  = (const float*)d_in[0];
    const void*  facesp = d_in[1];
    const float* K      = (const float*)d_in[2];
    const float* R      = (const float*)d_in[3];
    const float* t      = (const float*)d_in[4];
    const int*   osz    = (n_in >= 6) ? (const int*)d_in[5] : nullptr;

    int NF = in_sizes[1] / 3;   // skip reversed-winding duplicates (identical coverage)
    if (NF > NF_MAX) NF = NF_MAX;
    int NV = in_sizes[0] / 3;

    int* outi = (int*)d_out;
    init_kernel<<<(out_size + 255) / 256, 256>>>(outi, out_size);
    prep_kernel<<<(NF + 127) / 128, 128>>>(verts, facesp, K, R, t, osz, NF, NV);
    prefix_kernel<<<1, NBINS>>>();
    scatter_kernel<<<(NF + 127) / 128, 128>>>(NF);

    dim3 grid(NTILES, NSLICE);
    raster_kernel<<<grid, RTHREADS>>>(outi, NF);
}